// round 13
// baseline (speedup 1.0000x reference)
#include <cuda_runtime.h>
#include <cuda_bf16.h>
#include <math.h>
#include <stdint.h>

typedef __nv_bfloat16 bf16;

#define T_STEPS 4
#define LTOT    4096
#define DIM     256
#define ROWS    32768
#define PLANE   2097152
#define NELEM   8388608
#define REGION  64
#define HD      32
#define TOPK    4

#define GEMM_NS 4
#define GEMM_DSMEM (2 * GEMM_NS * 128 * 20 * 4 + 2048)

// ---------------- scratch (device globals) ----------------
__device__ bf16  g_s[NELEM];
__device__ bf16  g_qkv[25165824];     // qkv [32768,768] bf16
__device__ bf16  g_attn[NELEM];
__device__ bf16  g_h1[33554432];      // ffn hidden [32768,1024] bf16
__device__ float g_x2[NELEM];
__device__ bf16  g_wq[196608];
__device__ bf16  g_wp[65536];
__device__ bf16  g_w1[262144];
__device__ bf16  g_w2[262144];
__device__ float g_qm[131072];
__device__ float g_km[131072];
__device__ int   g_idx[2048];
__device__ float g_stats[512];

// ---------------- asm helpers ----------------
__device__ __forceinline__ void mma16816(float* c, const unsigned* a, const unsigned* b) {
    asm volatile(
        "mma.sync.aligned.m16n8k16.row.col.f32.bf16.bf16.f32 "
        "{%0,%1,%2,%3}, {%4,%5,%6,%7}, {%8,%9}, {%0,%1,%2,%3};"
        : "+f"(c[0]), "+f"(c[1]), "+f"(c[2]), "+f"(c[3])
        : "r"(a[0]), "r"(a[1]), "r"(a[2]), "r"(a[3]), "r"(b[0]), "r"(b[1]));
}
__device__ __forceinline__ uint32_t smem_u32(const void* p) {
    uint32_t a;
    asm("{ .reg .u64 t; cvta.to.shared.u64 t, %1; cvt.u32.u64 %0, t; }" : "=r"(a) : "l"(p));
    return a;
}
__device__ __forceinline__ void cp_async16(uint32_t s, const void* g) {
    asm volatile("cp.async.cg.shared.global [%0], [%1], 16;" :: "r"(s), "l"(g));
}
__device__ __forceinline__ void cp_commit() {
    asm volatile("cp.async.commit_group;" ::: "memory");
}
template<int N>
__device__ __forceinline__ void cp_wait() {
    asm volatile("cp.async.wait_group %0;" :: "n"(N) : "memory");
}
__device__ __forceinline__ void ldsm4(unsigned& r0, unsigned& r1, unsigned& r2, unsigned& r3,
                                      uint32_t addr) {
    asm volatile("ldmatrix.sync.aligned.m8n8.x4.shared.b16 {%0,%1,%2,%3}, [%4];"
                 : "=r"(r0), "=r"(r1), "=r"(r2), "=r"(r3) : "r"(addr));
}
__device__ __forceinline__ void ldsm4t(unsigned& r0, unsigned& r1, unsigned& r2, unsigned& r3,
                                       uint32_t addr) {
    asm volatile("ldmatrix.sync.aligned.m8n8.x4.trans.shared.b16 {%0,%1,%2,%3}, [%4];"
                 : "=r"(r0), "=r"(r1), "=r"(r2), "=r"(r3) : "r"(addr));
}

// ---------------- BN1 stats (kernel #1) ----------------
__global__ void stats_kernel(const float* __restrict__ x) {
    int d = threadIdx.x;
    int r0 = blockIdx.x * 128;
    float s = 0.f, ss = 0.f;
    #pragma unroll 4
    for (int r = 0; r < 128; r++) {
        float v = x[(size_t)(r0 + r) * DIM + d];
        s += v; ss += v * v;
    }
    atomicAdd(&g_stats[d], s);
    atomicAdd(&g_stats[256 + d], ss);
}

// ---------------- weight convert (kernel #2) ----------------
__global__ void cvt_kernel(const float* __restrict__ qkv_w, const float* __restrict__ proj_w,
                           const float* __restrict__ ffn_w1, const float* __restrict__ ffn_w2) {
    int i = blockIdx.x * 256 + threadIdx.x;
    if (i < 196608) g_wq[i] = __float2bfloat16(qkv_w[i]);
    else if (i < 262144) g_wp[i - 196608] = __float2bfloat16(proj_w[i - 196608]);
    else if (i < 524288) g_w1[i - 262144] = __float2bfloat16(ffn_w1[i - 262144]);
    else g_w2[i - 524288] = __float2bfloat16(ffn_w2[i - 524288]);
}

// BN-finalize (inline) + LIF; 4 consecutive elements per thread
__global__ void bn_lif_kernel(const float* __restrict__ x,
                              const float* __restrict__ gamma, const float* __restrict__ beta,
                              bf16* __restrict__ s) {
    int i4 = blockIdx.x * blockDim.x + threadIdx.x;
    size_t i = (size_t)i4 * 4;
    int d = (int)(i & (DIM - 1));
    float sc0, sc1, sc2, sc3, sh0, sh1, sh2, sh3;
    {
        #pragma unroll
        for (int e = 0; e < 4; e++) {
            float mean = g_stats[d + e] * (1.0f / 32768.0f);
            float var  = g_stats[256 + d + e] * (1.0f / 32768.0f) - mean * mean;
            float scv = rsqrtf(var + 1e-5f) * gamma[d + e];
            float shv = beta[d + e] - mean * scv;
            if (e == 0) { sc0 = scv; sh0 = shv; }
            else if (e == 1) { sc1 = scv; sh1 = shv; }
            else if (e == 2) { sc2 = scv; sh2 = shv; }
            else { sc3 = scv; sh3 = shv; }
        }
    }
    float v0 = 0.f, v1 = 0.f, v2 = 0.f, v3 = 0.f;
    #pragma unroll
    for (int t = 0; t < T_STEPS; t++) {
        float4 xv = *(const float4*)(x + (size_t)t * PLANE + i);
        float y0 = xv.x * sc0 + sh0, y1 = xv.y * sc1 + sh1;
        float y2 = xv.z * sc2 + sh2, y3 = xv.w * sc3 + sh3;
        v0 = 0.5f * (v0 + y0); v1 = 0.5f * (v1 + y1);
        v2 = 0.5f * (v2 + y2); v3 = 0.5f * (v3 + y3);
        float s0 = (v0 >= 1.0f) ? 1.0f : 0.0f;
        float s1 = (v1 >= 1.0f) ? 1.0f : 0.0f;
        float s2 = (v2 >= 1.0f) ? 1.0f : 0.0f;
        float s3 = (v3 >= 1.0f) ? 1.0f : 0.0f;
        __nv_bfloat162 p0 = __floats2bfloat162_rn(s0, s1);
        __nv_bfloat162 p1 = __floats2bfloat162_rn(s2, s3);
        uint2 st; st.x = *(unsigned*)&p0; st.y = *(unsigned*)&p1;
        *(uint2*)(s + (size_t)t * PLANE + i) = st;
        v0 = (s0 > 0.5f) ? 0.0f : v0; v1 = (s1 > 0.5f) ? 0.0f : v1;
        v2 = (s2 > 0.5f) ? 0.0f : v2; v3 = (s3 > 0.5f) ? 0.0f : v3;
    }
}

// ---------------- 4-stage cp.async 128x128 bf16 GEMM, ldmatrix mainloop ----------
template<int OUT_BF16, int GELU, int RESID, int STATS, int RSTATS>
__global__ void __launch_bounds__(256, 2)
mma_gemm(const bf16* __restrict__ A, const bf16* __restrict__ W,
         const float* __restrict__ bias, void* __restrict__ Cout,
         const float* __restrict__ resid, const float* __restrict__ scale_p,
         int N, int K) {
    extern __shared__ unsigned dynsm[];
    unsigned* Asm = dynsm;
    unsigned* Bsm = dynsm + GEMM_NS * 128 * 20;
    float* xsm = (float*)(dynsm + 2 * GEMM_NS * 128 * 20);

    int tid = threadIdx.x;
    int warp = tid >> 5, lane = tid & 31;
    int g = lane >> 2, tig = lane & 3;
    int wm = warp >> 1, wn = warp & 1;
    int m0 = blockIdx.y * 128, n0 = blockIdx.x * 128;

    int lr = tid >> 2;
    int lw = (tid & 3) * 4;
    int lc = (tid & 3) * 8;

    const bf16* Ap  = A + (size_t)(m0 + lr) * K + lc;
    const bf16* Ap2 = Ap + (size_t)64 * K;
    const bf16* Wp  = W + (size_t)(n0 + lr) * K + lc;
    const bf16* Wp2 = Wp + (size_t)64 * K;

    uint32_t sA = smem_u32(Asm), sB = smem_u32(Bsm);
    uint32_t ldoff = ((uint32_t)lr * 20 + lw) * 4;

    uint32_t aRow = ((wm * 32 + (lane & 15)) * 20 + (lane >> 4) * 4) * 4;
    uint32_t bRow = ((wn * 64 + (lane & 7) + ((lane >> 4) & 1) * 8) * 20 + ((lane >> 3) & 1) * 4) * 4;

    float acc[2][8][4];
    #pragma unroll
    for (int mi = 0; mi < 2; mi++)
        #pragma unroll
        for (int ni = 0; ni < 8; ni++)
            #pragma unroll
            for (int e = 0; e < 4; e++) acc[mi][ni][e] = 0.f;

    int n_st = K >> 5;

    #pragma unroll
    for (int st = 0; st < 3; st++) {
        size_t ko = (size_t)st << 5;
        uint32_t a0 = sA + st * 10240 + ldoff;
        uint32_t b0 = sB + st * 10240 + ldoff;
        cp_async16(a0,        Ap  + ko);
        cp_async16(a0 + 5120, Ap2 + ko);
        cp_async16(b0,        Wp  + ko);
        cp_async16(b0 + 5120, Wp2 + ko);
        cp_commit();
    }

    for (int it = 0; it < n_st; it++) {
        cp_wait<2>();
        __syncthreads();
        int pre = it + 3;
        if (pre < n_st) {
            int buf = pre & 3;
            size_t ko = (size_t)pre << 5;
            uint32_t a0 = sA + buf * 10240 + ldoff;
            uint32_t b0 = sB + buf * 10240 + ldoff;
            cp_async16(a0,        Ap  + ko);
            cp_async16(a0 + 5120, Ap2 + ko);
            cp_async16(b0,        Wp  + ko);
            cp_async16(b0 + 5120, Wp2 + ko);
        }
        cp_commit();

        uint32_t sAp = sA + (it & 3) * 10240;
        uint32_t sBp = sB + (it & 3) * 10240;
        #pragma unroll
        for (int ks = 0; ks < 2; ks++) {
            unsigned afr[2][4], bfr[8][2];
            #pragma unroll
            for (int mi = 0; mi < 2; mi++)
                ldsm4(afr[mi][0], afr[mi][1], afr[mi][2], afr[mi][3],
                      sAp + aRow + mi * 1280 + ks * 32);
            #pragma unroll
            for (int n2 = 0; n2 < 4; n2++)
                ldsm4(bfr[n2 * 2][0], bfr[n2 * 2][1], bfr[n2 * 2 + 1][0], bfr[n2 * 2 + 1][1],
                      sBp + bRow + n2 * 1280 + ks * 32);
            #pragma unroll
            for (int mi = 0; mi < 2; mi++)
                #pragma unroll
                for (int ni = 0; ni < 8; ni++)
                    mma16816(acc[mi][ni], afr[mi], bfr[ni]);
        }
    }

    // ---- epilogue ----
    float sc = RESID ? scale_p[0] : 0.f;
    float csum[16], csq[16];
    if (STATS || (RSTATS && n0 < 512)) {
        __syncthreads();
        if (tid < 256) { xsm[tid] = 0.f; if (STATS) xsm[256 + tid] = 0.f; }
        #pragma unroll
        for (int j = 0; j < 16; j++) { csum[j] = 0.f; csq[j] = 0.f; }
        __syncthreads();
    }

    #pragma unroll
    for (int mi = 0; mi < 2; mi++) {
        #pragma unroll
        for (int e2 = 0; e2 < 2; e2++) {
            int r = m0 + wm * 32 + mi * 16 + g + e2 * 8;
            #pragma unroll
            for (int ni = 0; ni < 8; ni++) {
                int c = n0 + wn * 64 + ni * 8 + tig * 2;
                float v0 = acc[mi][ni][e2 * 2]     + bias[c];
                float v1 = acc[mi][ni][e2 * 2 + 1] + bias[c + 1];
                if (GELU) {
                    v0 = 0.5f * v0 * (1.0f + erff(v0 * 0.70710678118654752f));
                    v1 = 0.5f * v1 * (1.0f + erff(v1 * 0.70710678118654752f));
                }
                size_t idx = (size_t)r * N + c;
                if (RESID) {
                    float2 rv = *(const float2*)(resid + idx);
                    v0 = rv.x + v0 * sc;
                    v1 = rv.y + v1 * sc;
                }
                if (STATS || RSTATS) {
                    csum[ni * 2]     += v0; csq[ni * 2]     += v0 * v0;
                    csum[ni * 2 + 1] += v1; csq[ni * 2 + 1] += v1 * v1;
                }
                if (OUT_BF16) {
                    __nv_bfloat162 pk = __floats2bfloat162_rn(v0, v1);
                    *(unsigned*)((bf16*)Cout + idx) = *(unsigned*)&pk;
                } else {
                    float2 f2; f2.x = v0; f2.y = v1;
                    *(float2*)((float*)Cout + idx) = f2;
                }
            }
        }
    }

    if (STATS) {
        #pragma unroll
        for (int j = 0; j < 16; j++) {
            int cl = wn * 64 + (j >> 1) * 8 + tig * 2 + (j & 1);
            atomicAdd(&xsm[cl], csum[j]);
            atomicAdd(&xsm[256 + cl], csq[j]);
        }
        __syncthreads();
        if (tid < 128) {
            atomicAdd(&g_stats[n0 + tid], xsm[tid]);
            atomicAdd(&g_stats[256 + n0 + tid], xsm[256 + tid]);
        }
    }

    if (RSTATS && n0 < 512) {
        #pragma unroll
        for (int j = 0; j < 16; j++) {
            csum[j] += __shfl_xor_sync(0xffffffffu, csum[j], 4);
            csum[j] += __shfl_xor_sync(0xffffffffu, csum[j], 8);
            csum[j] += __shfl_xor_sync(0xffffffffu, csum[j], 16);
        }
        int region = wm >> 1;
        if (g == 0) {
            #pragma unroll
            for (int j = 0; j < 16; j++) {
                int cl = wn * 64 + (j >> 1) * 8 + tig * 2 + (j & 1);
                atomicAdd(&xsm[region * 128 + cl], csum[j]);
            }
        }
        __syncthreads();
        if (tid < 256) {
            int rgn = tid >> 7, cl = tid & 127;
            float mv = xsm[tid] * (1.0f / 64.0f);
            int rb = (m0 >> 6) + rgn;
            int gc = n0 + cl;
            if (gc < 256) g_qm[rb * 256 + gc] = mv;
            else          g_km[rb * 256 + gc - 256] = mv;
        }
    }
}

// ---------------- affinity + top-4 routing: 64-thread blocks ----------------
__global__ void __launch_bounds__(64) aff_topk_kernel() {
    __shared__ float sq[256];
    __shared__ float aff[64];
    int blk = blockIdx.x;
    int b = blk >> 6;
    int t = threadIdx.x;

    *(float4*)&sq[t * 4] = *(const float4*)&g_qm[blk * 256 + t * 4];
    __syncthreads();

    const float* km = &g_km[((size_t)b * 64 + t) * 256];
    float s = 0.f;
    #pragma unroll 8
    for (int e = 0; e < 256; e += 4) {
        float4 kv = *(const float4*)(km + e);
        s += sq[e] * kv.x + sq[e + 1] * kv.y + sq[e + 2] * kv.z + sq[e + 3] * kv.w;
    }
    aff[t] = s;
    __syncthreads();

    if (t < 32) {
        float v0 = aff[t], v1 = aff[32 + t];
        #pragma unroll
        for (int k = 0; k < TOPK; k++) {
            float mv = (v1 > v0) ? v1 : v0;
            int   mi = (v1 > v0) ? (32 + t) : t;
            #pragma unroll
            for (int o = 16; o > 0; o >>= 1) {
                float ov = __shfl_xor_sync(0xffffffffu, mv, o);
                int   oi = __shfl_xor_sync(0xffffffffu, mi, o);
                if (ov > mv || (ov == mv && oi < mi)) { mv = ov; mi = oi; }
            }
            if (t == 0) g_idx[blk * TOPK + k] = mi;
            if (mi == t)      v0 = -INFINITY;
            if (mi == 32 + t) v1 = -INFINITY;
        }
    }
}

// ---------------- tensor-core flash attention (ldmatrix.trans V path) ----------------
#define KSTR 18
#define VSTR 20
__global__ void __launch_bounds__(128) attn_tc_kernel(const bf16* __restrict__ qkv,
                                                      bf16* __restrict__ o) {
    __shared__ unsigned sK[4][64][KSTR];
    __shared__ unsigned sV[4][64][VSTR];

    int tid = threadIdx.x;
    int w = tid >> 5, lane = tid & 31;
    int g = lane >> 2, tig = lane & 3;
    int hg = blockIdx.x, n = blockIdx.y, b = blockIdx.z;
    int h = hg * 4 + w;
    const float SCL = 0.17677669529663687f;

    unsigned (*Ks)[KSTR] = sK[w];
    unsigned (*Vs)[VSTR] = sV[w];
    uint32_t sVb = smem_u32(Vs);

    // ldmatrix.trans per-lane address components (constant across loop)
    int vt = lane >> 3;                       // tile index 0..3
    int vrow_off = ((vt & 1) << 3) + (lane & 7);
    uint32_t vcol = ((vt >> 1) << 4);         // (t>>1)*8 dims * 2 bytes

    unsigned qf[4][2][4];
    {
        const bf16* qb = qkv + ((size_t)b * LTOT + (size_t)n * REGION) * 768 + h * HD;
        #pragma unroll
        for (int mi = 0; mi < 4; mi++)
            #pragma unroll
            for (int s = 0; s < 2; s++) {
                int d0 = s * 16 + tig * 2;
                qf[mi][s][0] = *(const unsigned*)(qb + (size_t)(mi * 16 + g) * 768 + d0);
                qf[mi][s][1] = *(const unsigned*)(qb + (size_t)(mi * 16 + g + 8) * 768 + d0);
                qf[mi][s][2] = *(const unsigned*)(qb + (size_t)(mi * 16 + g) * 768 + d0 + 8);
                qf[mi][s][3] = *(const unsigned*)(qb + (size_t)(mi * 16 + g + 8) * 768 + d0 + 8);
            }
    }

    float sO[4][4][4];
    float mrow[4][2], lrow[4][2];
    #pragma unroll
    for (int mi = 0; mi < 4; mi++) {
        #pragma unroll
        for (int nd = 0; nd < 4; nd++)
            #pragma unroll
            for (int e = 0; e < 4; e++) sO[mi][nd][e] = 0.f;
        mrow[mi][0] = -1e30f; mrow[mi][1] = -1e30f;
        lrow[mi][0] = 0.f;    lrow[mi][1] = 0.f;
    }

    for (int r = 0; r < TOPK; r++) {
        int reg = g_idx[(b * 64 + n) * TOPK + r];
        size_t kvrow = ((size_t)b * LTOT + (size_t)reg * REGION) * 768;

        // K: two key rows per lane, vectorized
        #pragma unroll
        for (int rr = 0; rr < 2; rr++) {
            int key = lane * 2 + rr;
            const bf16* kb = qkv + kvrow + (size_t)key * 768 + 256 + h * HD;
            #pragma unroll
            for (int q4 = 0; q4 < 4; q4++) {
                uint4 v = *(const uint4*)(kb + q4 * 8);
                Ks[key][q4 * 4 + 0] = v.x; Ks[key][q4 * 4 + 1] = v.y;
                Ks[key][q4 * 4 + 2] = v.z; Ks[key][q4 * 4 + 3] = v.w;
            }
        }
        // V: one key row per lane (x2), vectorized uint4 stores (row-major; trans at load)
        #pragma unroll
        for (int kk = 0; kk < 2; kk++) {
            int key = kk * 32 + lane;
            const bf16* vb = qkv + kvrow + (size_t)key * 768 + 512 + h * HD;
            #pragma unroll
            for (int q4 = 0; q4 < 4; q4++) {
                uint4 v = *(const uint4*)(vb + q4 * 8);
                *(uint4*)&Vs[key][q4 * 4] = v;
            }
        }
        __syncwarp();

        #pragma unroll
        for (int sc = 0; sc < 2; sc++) {
            float sS[4][4][4];
            #pragma unroll
            for (int mi = 0; mi < 4; mi++)
                #pragma unroll
                for (int nj = 0; nj < 4; nj++)
                    #pragma unroll
                    for (int e = 0; e < 4; e++) sS[mi][nj][e] = 0.f;

            #pragma unroll
            for (int s = 0; s < 2; s++) {
                unsigned bfr[4][2];
                #pragma unroll
                for (int nj = 0; nj < 4; nj++) {
                    int kr = sc * 32 + nj * 8 + g;
                    bfr[nj][0] = Ks[kr][s * 8 + tig];
                    bfr[nj][1] = Ks[kr][s * 8 + tig + 4];
                }
                #pragma unroll
                for (int mi = 0; mi < 4; mi++)
                    #pragma unroll
                    for (int nj = 0; nj < 4; nj++)
                        mma16816(sS[mi][nj], qf[mi][s], bfr[nj]);
            }

            #pragma unroll
            for (int mi = 0; mi < 4; mi++) {
                #pragma unroll
                for (int hf = 0; hf < 2; hf++) {
                    float mx = -1e30f;
                    #pragma unroll
                    for (int nj = 0; nj < 4; nj++) {
                        float v0 = sS[mi][nj][hf * 2] * SCL;
                        float v1 = sS[mi][nj][hf * 2 + 1] * SCL;
                        sS[mi][nj][hf * 2] = v0; sS[mi][nj][hf * 2 + 1] = v1;
                        mx = fmaxf(mx, fmaxf(v0, v1));
                    }
                    mx = fmaxf(mx, __shfl_xor_sync(0xffffffffu, mx, 1));
                    mx = fmaxf(mx, __shfl_xor_sync(0xffffffffu, mx, 2));
                    float mnew = fmaxf(mrow[mi][hf], mx);
                    float alpha = __expf(mrow[mi][hf] - mnew);
                    mrow[mi][hf] = mnew;
                    float lsum = 0.f;
                    #pragma unroll
                    for (int nj = 0; nj < 4; nj++) {
                        float p0 = __expf(sS[mi][nj][hf * 2] - mnew);
                        float p1 = __expf(sS[mi][nj][hf * 2 + 1] - mnew);
                        sS[mi][nj][hf * 2] = p0; sS[mi][nj][hf * 2 + 1] = p1;
                        lsum += p0 + p1;
                    }
                    lsum += __shfl_xor_sync(0xffffffffu, lsum, 1);
                    lsum += __shfl_xor_sync(0xffffffffu, lsum, 2);
                    lrow[mi][hf] = lrow[mi][hf] * alpha + lsum;
                    #pragma unroll
                    for (int nd = 0; nd < 4; nd++) {
                        sO[mi][nd][hf * 2]     *= alpha;
                        sO[mi][nd][hf * 2 + 1] *= alpha;
                    }
                }
            }

            #pragma unroll
            for (int s = 0; s < 2; s++) {
                // V fragments via ldmatrix.trans: two x4 calls cover dims 0-15, 16-31
                unsigned bfr[4][2];
                int k0 = sc * 32 + s * 16;
                uint32_t rowaddr = sVb + (uint32_t)(k0 + vrow_off) * (VSTR * 4);
                ldsm4t(bfr[0][0], bfr[0][1], bfr[1][0], bfr[1][1], rowaddr + vcol);
                ldsm4t(bfr[2][0], bfr[2][1], bfr[3][0], bfr[3][1], rowaddr + vcol + 32);
                #pragma unroll
                for (int mi = 0; mi < 4; mi++) {
                    unsigned af[4];
                    __nv_bfloat162 t0 = __floats2bfloat162_rn(sS[mi][2 * s][0], sS[mi][2 * s][1]);
                    __nv_bfloat162 t1 = __floats2bfloat162_rn(sS[mi][2 * s][2], sS[mi][2 * s][3]);
                    __nv_bfloat162 t2 = __floats2bfloat162_rn(sS[mi][2 * s + 1][0], sS[mi][2 * s + 1][1]);
                    __nv_bfloat162 t3 = __floats2bfloat162_rn(sS[mi][2 * s + 1][2], sS[mi][2 * s + 1][3]);
                    af[0] = *(unsigned*)&t0; af[1] = *(unsigned*)&t1;
                    af[2] = *(unsigned*)&t2; af[3] = *(unsigned*)&t3;
                    #pragma unroll
                    for (int nd = 0; nd < 4; nd++)
                        mma16816(sO[mi][nd], af, bfr[nd]);
                }
            }
        }
        __syncwarp();
    }

    #pragma unroll
    for (int mi = 0; mi < 4; mi++) {
        float inv0 = 1.0f / lrow[mi][0];
        float inv1 = 1.0f / lrow[mi][1];
        #pragma unroll
        for (int hf = 0; hf < 2; hf++) {
            float inv = hf ? inv1 : inv0;
            size_t row = (size_t)b * LTOT + (size_t)n * REGION + mi * 16 + g + hf * 8;
            #pragma unroll
            for (int nd = 0; nd < 4; nd++) {
                float v0 = sO[mi][nd][hf * 2] * inv;
                float v1 = sO[mi][nd][hf * 2 + 1] * inv;
                __nv_bfloat162 p = __floats2bfloat162_rn(v0, v1);
                *(unsigned*)(o + row * DIM + h * HD + nd * 8 + tig * 2) = *(unsigned*)&p;
            }
        }
    }
}

// ---------------- host launcher ----------------
extern "C" void kernel_launch(void* const* d_in, const int* in_sizes, int n_in,
                              void* d_out, int out_size) {
    const float* x      = (const float*)d_in[0];
    const float* bn1_g  = (const float*)d_in[1];
    const float* bn1_b  = (const float*)d_in[2];
    const float* bn2_g  = (const float*)d_in[3];
    const float* bn2_b  = (const float*)d_in[4];
    const float* qkv_w  = (const float*)d_in[5];
    const float* qkv_b  = (const float*)d_in[6];
    const float* proj_w = (const float*)d_in[7];
    const float* proj_b = (const float*)d_in[8];
    const float* ffn_w1 = (const float*)d_in[9];
    const float* ffn_b1 = (const float*)d_in[10];
    const float* ffn_w2 = (const float*)d_in[11];
    const float* ffn_b2 = (const float*)d_in[12];
    const float* scale  = (const float*)d_in[13];
    float* out = (float*)d_out;

    cudaFuncSetAttribute(mma_gemm<1, 0, 0, 0, 1>, cudaFuncAttributeMaxDynamicSharedMemorySize, GEMM_DSMEM);
    cudaFuncSetAttribute(mma_gemm<0, 0, 1, 1, 0>, cudaFuncAttributeMaxDynamicSharedMemorySize, GEMM_DSMEM);
    cudaFuncSetAttribute(mma_gemm<1, 1, 0, 0, 0>, cudaFuncAttributeMaxDynamicSharedMemorySize, GEMM_DSMEM);
    cudaFuncSetAttribute(mma_gemm<0, 0, 1, 0, 0>, cudaFuncAttributeMaxDynamicSharedMemorySize, GEMM_DSMEM);

    bf16*  s    = nullptr; cudaGetSymbolAddress((void**)&s,    g_s);
    bf16*  qkv  = nullptr; cudaGetSymbolAddress((void**)&qkv,  g_qkv);
    bf16*  attn = nullptr; cudaGetSymbolAddress((void**)&attn, g_attn);
    bf16*  h1   = nullptr; cudaGetSymbolAddress((void**)&h1,   g_h1);
    float* x2   = nullptr; cudaGetSymbolAddress((void**)&x2,   g_x2);
    bf16*  wq   = nullptr; cudaGetSymbolAddress((void**)&wq,   g_wq);
    bf16*  wp   = nullptr; cudaGetSymbolAddress((void**)&wp,   g_wp);
    bf16*  w1   = nullptr; cudaGetSymbolAddress((void**)&w1,   g_w1);
    bf16*  w2   = nullptr; cudaGetSymbolAddress((void**)&w2,   g_w2);
    float* stats = nullptr; cudaGetSymbolAddress((void**)&stats, g_stats);

    // ---- attention branch ----
    cudaMemsetAsync(stats, 0, 512 * sizeof(float));
    stats_kernel<<<256, 256>>>(x);                               // kernel #1
    cvt_kernel<<<3072, 256>>>(qkv_w, proj_w, ffn_w1, ffn_w2);    // kernel #2
    bn_lif_kernel<<<PLANE / 1024, 256>>>(x, bn1_g, bn1_b, s);    // kernel #3

    cudaMemsetAsync(stats, 0, 512 * sizeof(float));              // zero for BN2 accumulation

    // kernel #4 (ncu-profiled slot): qkv GEMM with fused region means
    mma_gemm<1, 0, 0, 0, 1><<<dim3(6, 256), 256, GEMM_DSMEM>>>(s, wq, qkv_b, qkv, nullptr, nullptr, 768, 256);

    aff_topk_kernel<<<512, 64>>>();
    attn_tc_kernel<<<dim3(2, 64, 8), 128>>>(qkv, attn);

    // proj GEMM fused with residual (x2 = x + v*scale) + BN2 stats
    mma_gemm<0, 0, 1, 1, 0><<<dim3(2, 256), 256, GEMM_DSMEM>>>(attn, wp, proj_b, x2, x, scale, 256, 256);

    bn_lif_kernel<<<PLANE / 1024, 256>>>(x2, bn2_g, bn2_b, s);

    mma_gemm<1, 1, 0, 0, 0><<<dim3(8, 256), 256, GEMM_DSMEM>>>(s, w1, ffn_b1, h1, nullptr, nullptr, 1024, 256);
    // ffn2 GEMM fused with final residual (out = x2 + v*scale)
    mma_gemm<0, 0, 1, 0, 0><<<dim3(2, 256), 256, GEMM_DSMEM>>>(h1, w2, ffn_b2, out, x2, scale, 256, 1024);
}

// round 14
// speedup vs baseline: 1.0038x; 1.0038x over previous
#include <cuda_runtime.h>
#include <cuda_bf16.h>
#include <math.h>
#include <stdint.h>

typedef __nv_bfloat16 bf16;

#define T_STEPS 4
#define LTOT    4096
#define DIM     256
#define ROWS    32768
#define PLANE   2097152
#define NELEM   8388608
#define REGION  64
#define HD      32
#define TOPK    4

#define GEMM_NS 4
// A: [NS][128][20] u32, B: [NS][64][20] u32, + 2KB scratch
#define GEMM_DSMEM ((GEMM_NS * 128 * 20 + GEMM_NS * 64 * 20) * 4 + 2048)

// ---------------- scratch (device globals) ----------------
__device__ bf16  g_s[NELEM];
__device__ bf16  g_qkv[25165824];     // qkv [32768,768] bf16
__device__ bf16  g_attn[NELEM];
__device__ bf16  g_h1[33554432];      // ffn hidden [32768,1024] bf16
__device__ float g_x2[NELEM];
__device__ bf16  g_wq[196608];
__device__ bf16  g_wp[65536];
__device__ bf16  g_w1[262144];
__device__ bf16  g_w2[262144];
__device__ float g_qm[131072];
__device__ float g_km[131072];
__device__ int   g_idx[2048];
__device__ float g_stats[512];

// ---------------- asm helpers ----------------
__device__ __forceinline__ void mma16816(float* c, const unsigned* a, const unsigned* b) {
    asm volatile(
        "mma.sync.aligned.m16n8k16.row.col.f32.bf16.bf16.f32 "
        "{%0,%1,%2,%3}, {%4,%5,%6,%7}, {%8,%9}, {%0,%1,%2,%3};"
        : "+f"(c[0]), "+f"(c[1]), "+f"(c[2]), "+f"(c[3])
        : "r"(a[0]), "r"(a[1]), "r"(a[2]), "r"(a[3]), "r"(b[0]), "r"(b[1]));
}
__device__ __forceinline__ uint32_t smem_u32(const void* p) {
    uint32_t a;
    asm("{ .reg .u64 t; cvta.to.shared.u64 t, %1; cvt.u32.u64 %0, t; }" : "=r"(a) : "l"(p));
    return a;
}
__device__ __forceinline__ void cp_async16(uint32_t s, const void* g) {
    asm volatile("cp.async.cg.shared.global [%0], [%1], 16;" :: "r"(s), "l"(g));
}
__device__ __forceinline__ void cp_commit() {
    asm volatile("cp.async.commit_group;" ::: "memory");
}
template<int N>
__device__ __forceinline__ void cp_wait() {
    asm volatile("cp.async.wait_group %0;" :: "n"(N) : "memory");
}
__device__ __forceinline__ void ldsm4(unsigned& r0, unsigned& r1, unsigned& r2, unsigned& r3,
                                      uint32_t addr) {
    asm volatile("ldmatrix.sync.aligned.m8n8.x4.shared.b16 {%0,%1,%2,%3}, [%4];"
                 : "=r"(r0), "=r"(r1), "=r"(r2), "=r"(r3) : "r"(addr));
}
__device__ __forceinline__ void ldsm4t(unsigned& r0, unsigned& r1, unsigned& r2, unsigned& r3,
                                       uint32_t addr) {
    asm volatile("ldmatrix.sync.aligned.m8n8.x4.trans.shared.b16 {%0,%1,%2,%3}, [%4];"
                 : "=r"(r0), "=r"(r1), "=r"(r2), "=r"(r3) : "r"(addr));
}

// ---------------- BN1 stats (kernel #1) ----------------
__global__ void stats_kernel(const float* __restrict__ x) {
    int d = threadIdx.x;
    int r0 = blockIdx.x * 128;
    float s = 0.f, ss = 0.f;
    #pragma unroll 4
    for (int r = 0; r < 128; r++) {
        float v = x[(size_t)(r0 + r) * DIM + d];
        s += v; ss += v * v;
    }
    atomicAdd(&g_stats[d], s);
    atomicAdd(&g_stats[256 + d], ss);
}

// ---------------- weight convert (kernel #2) ----------------
__global__ void cvt_kernel(const float* __restrict__ qkv_w, const float* __restrict__ proj_w,
                           const float* __restrict__ ffn_w1, const float* __restrict__ ffn_w2) {
    int i = blockIdx.x * 256 + threadIdx.x;
    if (i < 196608) g_wq[i] = __float2bfloat16(qkv_w[i]);
    else if (i < 262144) g_wp[i - 196608] = __float2bfloat16(proj_w[i - 196608]);
    else if (i < 524288) g_w1[i - 262144] = __float2bfloat16(ffn_w1[i - 262144]);
    else g_w2[i - 524288] = __float2bfloat16(ffn_w2[i - 524288]);
}

// BN-finalize (inline) + LIF; 4 consecutive elements per thread
__global__ void bn_lif_kernel(const float* __restrict__ x,
                              const float* __restrict__ gamma, const float* __restrict__ beta,
                              bf16* __restrict__ s) {
    int i4 = blockIdx.x * blockDim.x + threadIdx.x;
    size_t i = (size_t)i4 * 4;
    int d = (int)(i & (DIM - 1));
    float sc0, sc1, sc2, sc3, sh0, sh1, sh2, sh3;
    {
        #pragma unroll
        for (int e = 0; e < 4; e++) {
            float mean = g_stats[d + e] * (1.0f / 32768.0f);
            float var  = g_stats[256 + d + e] * (1.0f / 32768.0f) - mean * mean;
            float scv = rsqrtf(var + 1e-5f) * gamma[d + e];
            float shv = beta[d + e] - mean * scv;
            if (e == 0) { sc0 = scv; sh0 = shv; }
            else if (e == 1) { sc1 = scv; sh1 = shv; }
            else if (e == 2) { sc2 = scv; sh2 = shv; }
            else { sc3 = scv; sh3 = shv; }
        }
    }
    float v0 = 0.f, v1 = 0.f, v2 = 0.f, v3 = 0.f;
    #pragma unroll
    for (int t = 0; t < T_STEPS; t++) {
        float4 xv = *(const float4*)(x + (size_t)t * PLANE + i);
        float y0 = xv.x * sc0 + sh0, y1 = xv.y * sc1 + sh1;
        float y2 = xv.z * sc2 + sh2, y3 = xv.w * sc3 + sh3;
        v0 = 0.5f * (v0 + y0); v1 = 0.5f * (v1 + y1);
        v2 = 0.5f * (v2 + y2); v3 = 0.5f * (v3 + y3);
        float s0 = (v0 >= 1.0f) ? 1.0f : 0.0f;
        float s1 = (v1 >= 1.0f) ? 1.0f : 0.0f;
        float s2 = (v2 >= 1.0f) ? 1.0f : 0.0f;
        float s3 = (v3 >= 1.0f) ? 1.0f : 0.0f;
        __nv_bfloat162 p0 = __floats2bfloat162_rn(s0, s1);
        __nv_bfloat162 p1 = __floats2bfloat162_rn(s2, s3);
        uint2 st; st.x = *(unsigned*)&p0; st.y = *(unsigned*)&p1;
        *(uint2*)(s + (size_t)t * PLANE + i) = st;
        v0 = (s0 > 0.5f) ? 0.0f : v0; v1 = (s1 > 0.5f) ? 0.0f : v1;
        v2 = (s2 > 0.5f) ? 0.0f : v2; v3 = (s3 > 0.5f) ? 0.0f : v3;
    }
}

// ---------------- 4-stage cp.async 128x64 bf16 GEMM (3 CTAs/SM target) ----------
// warps: 8 = 4(m) x 2(n); each warp 32 rows x 32 cols
template<int OUT_BF16, int GELU, int RESID, int STATS, int RSTATS>
__global__ void __launch_bounds__(256, 3)
mma_gemm(const bf16* __restrict__ A, const bf16* __restrict__ W,
         const float* __restrict__ bias, void* __restrict__ Cout,
         const float* __restrict__ resid, const float* __restrict__ scale_p,
         int N, int K) {
    extern __shared__ unsigned dynsm[];
    unsigned* Asm = dynsm;                                   // [NS][128][20]
    unsigned* Bsm = dynsm + GEMM_NS * 128 * 20;              // [NS][64][20]
    float* xsm = (float*)(dynsm + GEMM_NS * 128 * 20 + GEMM_NS * 64 * 20);  // 128 floats

    int tid = threadIdx.x;
    int warp = tid >> 5, lane = tid & 31;
    int g = lane >> 2, tig = lane & 3;
    int wm = warp >> 1, wn = warp & 1;
    int m0 = blockIdx.y * 128, n0 = blockIdx.x * 64;

    int lr = tid >> 2;            // 0..63
    int lw = (tid & 3) * 4;
    int lc = (tid & 3) * 8;

    const bf16* Ap  = A + (size_t)(m0 + lr) * K + lc;
    const bf16* Ap2 = Ap + (size_t)64 * K;
    const bf16* Wp  = W + (size_t)(n0 + lr) * K + lc;

    uint32_t sA = smem_u32(Asm), sB = smem_u32(Bsm);
    uint32_t ldoff = ((uint32_t)lr * 20 + lw) * 4;

    uint32_t aRow = ((wm * 32 + (lane & 15)) * 20 + (lane >> 4) * 4) * 4;
    uint32_t bRow = ((wn * 32 + (lane & 7) + ((lane >> 4) & 1) * 8) * 20 + ((lane >> 3) & 1) * 4) * 4;

    float acc[2][4][4];
    #pragma unroll
    for (int mi = 0; mi < 2; mi++)
        #pragma unroll
        for (int ni = 0; ni < 4; ni++)
            #pragma unroll
            for (int e = 0; e < 4; e++) acc[mi][ni][e] = 0.f;

    int n_st = K >> 5;

    #pragma unroll
    for (int st = 0; st < 3; st++) {
        size_t ko = (size_t)st << 5;
        uint32_t a0 = sA + st * 10240 + ldoff;
        uint32_t b0 = sB + st * 5120 + ldoff;
        cp_async16(a0,        Ap  + ko);
        cp_async16(a0 + 5120, Ap2 + ko);
        cp_async16(b0,        Wp  + ko);
        cp_commit();
    }

    for (int it = 0; it < n_st; it++) {
        cp_wait<2>();
        __syncthreads();
        int pre = it + 3;
        if (pre < n_st) {
            int buf = pre & 3;
            size_t ko = (size_t)pre << 5;
            uint32_t a0 = sA + buf * 10240 + ldoff;
            uint32_t b0 = sB + buf * 5120 + ldoff;
            cp_async16(a0,        Ap  + ko);
            cp_async16(a0 + 5120, Ap2 + ko);
            cp_async16(b0,        Wp  + ko);
        }
        cp_commit();

        uint32_t sAp = sA + (it & 3) * 10240;
        uint32_t sBp = sB + (it & 3) * 5120;
        #pragma unroll
        for (int ks = 0; ks < 2; ks++) {
            unsigned afr[2][4], bfr[4][2];
            #pragma unroll
            for (int mi = 0; mi < 2; mi++)
                ldsm4(afr[mi][0], afr[mi][1], afr[mi][2], afr[mi][3],
                      sAp + aRow + mi * 1280 + ks * 32);
            #pragma unroll
            for (int n2 = 0; n2 < 2; n2++)
                ldsm4(bfr[n2 * 2][0], bfr[n2 * 2][1], bfr[n2 * 2 + 1][0], bfr[n2 * 2 + 1][1],
                      sBp + bRow + n2 * 1280 + ks * 32);
            #pragma unroll
            for (int mi = 0; mi < 2; mi++)
                #pragma unroll
                for (int ni = 0; ni < 4; ni++)
                    mma16816(acc[mi][ni], afr[mi], bfr[ni]);
        }
    }

    // ---- epilogue ----
    float sc = RESID ? scale_p[0] : 0.f;
    float csum[8], csq[8];
    if (STATS || (RSTATS && n0 < 512)) {
        __syncthreads();
        if (tid < 128) xsm[tid] = 0.f;
        #pragma unroll
        for (int j = 0; j < 8; j++) { csum[j] = 0.f; csq[j] = 0.f; }
        __syncthreads();
    }

    #pragma unroll
    for (int mi = 0; mi < 2; mi++) {
        #pragma unroll
        for (int e2 = 0; e2 < 2; e2++) {
            int r = m0 + wm * 32 + mi * 16 + g + e2 * 8;
            #pragma unroll
            for (int ni = 0; ni < 4; ni++) {
                int c = n0 + wn * 32 + ni * 8 + tig * 2;
                float v0 = acc[mi][ni][e2 * 2]     + bias[c];
                float v1 = acc[mi][ni][e2 * 2 + 1] + bias[c + 1];
                if (GELU) {
                    v0 = 0.5f * v0 * (1.0f + erff(v0 * 0.70710678118654752f));
                    v1 = 0.5f * v1 * (1.0f + erff(v1 * 0.70710678118654752f));
                }
                size_t idx = (size_t)r * N + c;
                if (RESID) {
                    float2 rv = *(const float2*)(resid + idx);
                    v0 = rv.x + v0 * sc;
                    v1 = rv.y + v1 * sc;
                }
                if (STATS || RSTATS) {
                    csum[ni * 2]     += v0; csq[ni * 2]     += v0 * v0;
                    csum[ni * 2 + 1] += v1; csq[ni * 2 + 1] += v1 * v1;
                }
                if (OUT_BF16) {
                    __nv_bfloat162 pk = __floats2bfloat162_rn(v0, v1);
                    *(unsigned*)((bf16*)Cout + idx) = *(unsigned*)&pk;
                } else {
                    float2 f2; f2.x = v0; f2.y = v1;
                    *(float2*)((float*)Cout + idx) = f2;
                }
            }
        }
    }

    if (STATS) {
        // xsm[0..63] = col sums, xsm[64..127] = col sumsq
        #pragma unroll
        for (int j = 0; j < 8; j++) {
            int cl = wn * 32 + (j >> 1) * 8 + tig * 2 + (j & 1);
            atomicAdd(&xsm[cl], csum[j]);
            atomicAdd(&xsm[64 + cl], csq[j]);
        }
        __syncthreads();
        if (tid < 64) {
            atomicAdd(&g_stats[n0 + tid], xsm[tid]);
            atomicAdd(&g_stats[256 + n0 + tid], xsm[64 + tid]);
        }
    }

    if (RSTATS && n0 < 512) {
        // per-region (64-row) column sums; xsm[region*64 + col]
        #pragma unroll
        for (int j = 0; j < 8; j++) {
            csum[j] += __shfl_xor_sync(0xffffffffu, csum[j], 4);
            csum[j] += __shfl_xor_sync(0xffffffffu, csum[j], 8);
            csum[j] += __shfl_xor_sync(0xffffffffu, csum[j], 16);
        }
        int region = wm >> 1;
        if (g == 0) {
            #pragma unroll
            for (int j = 0; j < 8; j++) {
                int cl = wn * 32 + (j >> 1) * 8 + tig * 2 + (j & 1);
                atomicAdd(&xsm[region * 64 + cl], csum[j]);
            }
        }
        __syncthreads();
        if (tid < 128) {
            int rgn = tid >> 6, cl = tid & 63;
            float mv = xsm[tid] * (1.0f / 64.0f);
            int rb = (m0 >> 6) + rgn;
            int gc = n0 + cl;
            if (gc < 256) g_qm[rb * 256 + gc] = mv;
            else          g_km[rb * 256 + gc - 256] = mv;
        }
    }
}

// ---------------- affinity + top-4 routing: 64-thread blocks ----------------
__global__ void __launch_bounds__(64) aff_topk_kernel() {
    __shared__ float sq[256];
    __shared__ float aff[64];
    int blk = blockIdx.x;
    int b = blk >> 6;
    int t = threadIdx.x;

    *(float4*)&sq[t * 4] = *(const float4*)&g_qm[blk * 256 + t * 4];
    __syncthreads();

    const float* km = &g_km[((size_t)b * 64 + t) * 256];
    float s = 0.f;
    #pragma unroll 8
    for (int e = 0; e < 256; e += 4) {
        float4 kv = *(const float4*)(km + e);
        s += sq[e] * kv.x + sq[e + 1] * kv.y + sq[e + 2] * kv.z + sq[e + 3] * kv.w;
    }
    aff[t] = s;
    __syncthreads();

    if (t < 32) {
        float v0 = aff[t], v1 = aff[32 + t];
        #pragma unroll
        for (int k = 0; k < TOPK; k++) {
            float mv = (v1 > v0) ? v1 : v0;
            int   mi = (v1 > v0) ? (32 + t) : t;
            #pragma unroll
            for (int o = 16; o > 0; o >>= 1) {
                float ov = __shfl_xor_sync(0xffffffffu, mv, o);
                int   oi = __shfl_xor_sync(0xffffffffu, mi, o);
                if (ov > mv || (ov == mv && oi < mi)) { mv = ov; mi = oi; }
            }
            if (t == 0) g_idx[blk * TOPK + k] = mi;
            if (mi == t)      v0 = -INFINITY;
            if (mi == 32 + t) v1 = -INFINITY;
        }
    }
}

// ---------------- tensor-core flash attention (ldmatrix.trans V path) ----------------
#define KSTR 18
#define VSTR 20
__global__ void __launch_bounds__(128) attn_tc_kernel(const bf16* __restrict__ qkv,
                                                      bf16* __restrict__ o) {
    __shared__ unsigned sK[4][64][KSTR];
    __shared__ unsigned sV[4][64][VSTR];

    int tid = threadIdx.x;
    int w = tid >> 5, lane = tid & 31;
    int g = lane >> 2, tig = lane & 3;
    int hg = blockIdx.x, n = blockIdx.y, b = blockIdx.z;
    int h = hg * 4 + w;
    const float SCL = 0.17677669529663687f;

    unsigned (*Ks)[KSTR] = sK[w];
    unsigned (*Vs)[VSTR] = sV[w];
    uint32_t sVb = smem_u32(Vs);

    int vt = lane >> 3;
    int vrow_off = ((vt & 1) << 3) + (lane & 7);
    uint32_t vcol = ((vt >> 1) << 4);

    unsigned qf[4][2][4];
    {
        const bf16* qb = qkv + ((size_t)b * LTOT + (size_t)n * REGION) * 768 + h * HD;
        #pragma unroll
        for (int mi = 0; mi < 4; mi++)
            #pragma unroll
            for (int s = 0; s < 2; s++) {
                int d0 = s * 16 + tig * 2;
                qf[mi][s][0] = *(const unsigned*)(qb + (size_t)(mi * 16 + g) * 768 + d0);
                qf[mi][s][1] = *(const unsigned*)(qb + (size_t)(mi * 16 + g + 8) * 768 + d0);
                qf[mi][s][2] = *(const unsigned*)(qb + (size_t)(mi * 16 + g) * 768 + d0 + 8);
                qf[mi][s][3] = *(const unsigned*)(qb + (size_t)(mi * 16 + g + 8) * 768 + d0 + 8);
            }
    }

    float sO[4][4][4];
    float mrow[4][2], lrow[4][2];
    #pragma unroll
    for (int mi = 0; mi < 4; mi++) {
        #pragma unroll
        for (int nd = 0; nd < 4; nd++)
            #pragma unroll
            for (int e = 0; e < 4; e++) sO[mi][nd][e] = 0.f;
        mrow[mi][0] = -1e30f; mrow[mi][1] = -1e30f;
        lrow[mi][0] = 0.f;    lrow[mi][1] = 0.f;
    }

    for (int r = 0; r < TOPK; r++) {
        int reg = g_idx[(b * 64 + n) * TOPK + r];
        size_t kvrow = ((size_t)b * LTOT + (size_t)reg * REGION) * 768;

        #pragma unroll
        for (int rr = 0; rr < 2; rr++) {
            int key = lane * 2 + rr;
            const bf16* kb = qkv + kvrow + (size_t)key * 768 + 256 + h * HD;
            #pragma unroll
            for (int q4 = 0; q4 < 4; q4++) {
                uint4 v = *(const uint4*)(kb + q4 * 8);
                Ks[key][q4 * 4 + 0] = v.x; Ks[key][q4 * 4 + 1] = v.y;
                Ks[key][q4 * 4 + 2] = v.z; Ks[key][q4 * 4 + 3] = v.w;
            }
        }
        #pragma unroll
        for (int kk = 0; kk < 2; kk++) {
            int key = kk * 32 + lane;
            const bf16* vb = qkv + kvrow + (size_t)key * 768 + 512 + h * HD;
            #pragma unroll
            for (int q4 = 0; q4 < 4; q4++) {
                uint4 v = *(const uint4*)(vb + q4 * 8);
                *(uint4*)&Vs[key][q4 * 4] = v;
            }
        }
        __syncwarp();

        #pragma unroll
        for (int sc = 0; sc < 2; sc++) {
            float sS[4][4][4];
            #pragma unroll
            for (int mi = 0; mi < 4; mi++)
                #pragma unroll
                for (int nj = 0; nj < 4; nj++)
                    #pragma unroll
                    for (int e = 0; e < 4; e++) sS[mi][nj][e] = 0.f;

            #pragma unroll
            for (int s = 0; s < 2; s++) {
                unsigned bfr[4][2];
                #pragma unroll
                for (int nj = 0; nj < 4; nj++) {
                    int kr = sc * 32 + nj * 8 + g;
                    bfr[nj][0] = Ks[kr][s * 8 + tig];
                    bfr[nj][1] = Ks[kr][s * 8 + tig + 4];
                }
                #pragma unroll
                for (int mi = 0; mi < 4; mi++)
                    #pragma unroll
                    for (int nj = 0; nj < 4; nj++)
                        mma16816(sS[mi][nj], qf[mi][s], bfr[nj]);
            }

            #pragma unroll
            for (int mi = 0; mi < 4; mi++) {
                #pragma unroll
                for (int hf = 0; hf < 2; hf++) {
                    float mx = -1e30f;
                    #pragma unroll
                    for (int nj = 0; nj < 4; nj++) {
                        float v0 = sS[mi][nj][hf * 2] * SCL;
                        float v1 = sS[mi][nj][hf * 2 + 1] * SCL;
                        sS[mi][nj][hf * 2] = v0; sS[mi][nj][hf * 2 + 1] = v1;
                        mx = fmaxf(mx, fmaxf(v0, v1));
                    }
                    mx = fmaxf(mx, __shfl_xor_sync(0xffffffffu, mx, 1));
                    mx = fmaxf(mx, __shfl_xor_sync(0xffffffffu, mx, 2));
                    float mnew = fmaxf(mrow[mi][hf], mx);
                    float alpha = __expf(mrow[mi][hf] - mnew);
                    mrow[mi][hf] = mnew;
                    float lsum = 0.f;
                    #pragma unroll
                    for (int nj = 0; nj < 4; nj++) {
                        float p0 = __expf(sS[mi][nj][hf * 2] - mnew);
                        float p1 = __expf(sS[mi][nj][hf * 2 + 1] - mnew);
                        sS[mi][nj][hf * 2] = p0; sS[mi][nj][hf * 2 + 1] = p1;
                        lsum += p0 + p1;
                    }
                    lsum += __shfl_xor_sync(0xffffffffu, lsum, 1);
                    lsum += __shfl_xor_sync(0xffffffffu, lsum, 2);
                    lrow[mi][hf] = lrow[mi][hf] * alpha + lsum;
                    #pragma unroll
                    for (int nd = 0; nd < 4; nd++) {
                        sO[mi][nd][hf * 2]     *= alpha;
                        sO[mi][nd][hf * 2 + 1] *= alpha;
                    }
                }
            }

            #pragma unroll
            for (int s = 0; s < 2; s++) {
                unsigned bfr[4][2];
                int k0 = sc * 32 + s * 16;
                uint32_t rowaddr = sVb + (uint32_t)(k0 + vrow_off) * (VSTR * 4);
                ldsm4t(bfr[0][0], bfr[0][1], bfr[1][0], bfr[1][1], rowaddr + vcol);
                ldsm4t(bfr[2][0], bfr[2][1], bfr[3][0], bfr[3][1], rowaddr + vcol + 32);
                #pragma unroll
                for (int mi = 0; mi < 4; mi++) {
                    unsigned af[4];
                    __nv_bfloat162 t0 = __floats2bfloat162_rn(sS[mi][2 * s][0], sS[mi][2 * s][1]);
                    __nv_bfloat162 t1 = __floats2bfloat162_rn(sS[mi][2 * s][2], sS[mi][2 * s][3]);
                    __nv_bfloat162 t2 = __floats2bfloat162_rn(sS[mi][2 * s + 1][0], sS[mi][2 * s + 1][1]);
                    __nv_bfloat162 t3 = __floats2bfloat162_rn(sS[mi][2 * s + 1][2], sS[mi][2 * s + 1][3]);
                    af[0] = *(unsigned*)&t0; af[1] = *(unsigned*)&t1;
                    af[2] = *(unsigned*)&t2; af[3] = *(unsigned*)&t3;
                    #pragma unroll
                    for (int nd = 0; nd < 4; nd++)
                        mma16816(sO[mi][nd], af, bfr[nd]);
                }
            }
        }
        __syncwarp();
    }

    #pragma unroll
    for (int mi = 0; mi < 4; mi++) {
        float inv0 = 1.0f / lrow[mi][0];
        float inv1 = 1.0f / lrow[mi][1];
        #pragma unroll
        for (int hf = 0; hf < 2; hf++) {
            float inv = hf ? inv1 : inv0;
            size_t row = (size_t)b * LTOT + (size_t)n * REGION + mi * 16 + g + hf * 8;
            #pragma unroll
            for (int nd = 0; nd < 4; nd++) {
                float v0 = sO[mi][nd][hf * 2] * inv;
                float v1 = sO[mi][nd][hf * 2 + 1] * inv;
                __nv_bfloat162 p = __floats2bfloat162_rn(v0, v1);
                *(unsigned*)(o + row * DIM + h * HD + nd * 8 + tig * 2) = *(unsigned*)&p;
            }
        }
    }
}

// ---------------- host launcher ----------------
extern "C" void kernel_launch(void* const* d_in, const int* in_sizes, int n_in,
                              void* d_out, int out_size) {
    const float* x      = (const float*)d_in[0];
    const float* bn1_g  = (const float*)d_in[1];
    const float* bn1_b  = (const float*)d_in[2];
    const float* bn2_g  = (const float*)d_in[3];
    const float* bn2_b  = (const float*)d_in[4];
    const float* qkv_w  = (const float*)d_in[5];
    const float* qkv_b  = (const float*)d_in[6];
    const float* proj_w = (const float*)d_in[7];
    const float* proj_b = (const float*)d_in[8];
    const float* ffn_w1 = (const float*)d_in[9];
    const float* ffn_b1 = (const float*)d_in[10];
    const float* ffn_w2 = (const float*)d_in[11];
    const float* ffn_b2 = (const float*)d_in[12];
    const float* scale  = (const float*)d_in[13];
    float* out = (float*)d_out;

    cudaFuncSetAttribute(mma_gemm<1, 0, 0, 0, 1>, cudaFuncAttributeMaxDynamicSharedMemorySize, GEMM_DSMEM);
    cudaFuncSetAttribute(mma_gemm<0, 0, 1, 1, 0>, cudaFuncAttributeMaxDynamicSharedMemorySize, GEMM_DSMEM);
    cudaFuncSetAttribute(mma_gemm<1, 1, 0, 0, 0>, cudaFuncAttributeMaxDynamicSharedMemorySize, GEMM_DSMEM);
    cudaFuncSetAttribute(mma_gemm<0, 0, 1, 0, 0>, cudaFuncAttributeMaxDynamicSharedMemorySize, GEMM_DSMEM);

    bf16*  s    = nullptr; cudaGetSymbolAddress((void**)&s,    g_s);
    bf16*  qkv  = nullptr; cudaGetSymbolAddress((void**)&qkv,  g_qkv);
    bf16*  attn = nullptr; cudaGetSymbolAddress((void**)&attn, g_attn);
    bf16*  h1   = nullptr; cudaGetSymbolAddress((void**)&h1,   g_h1);
    float* x2   = nullptr; cudaGetSymbolAddress((void**)&x2,   g_x2);
    bf16*  wq   = nullptr; cudaGetSymbolAddress((void**)&wq,   g_wq);
    bf16*  wp   = nullptr; cudaGetSymbolAddress((void**)&wp,   g_wp);
    bf16*  w1   = nullptr; cudaGetSymbolAddress((void**)&w1,   g_w1);
    bf16*  w2   = nullptr; cudaGetSymbolAddress((void**)&w2,   g_w2);
    float* stats = nullptr; cudaGetSymbolAddress((void**)&stats, g_stats);

    // ---- attention branch ----
    cudaMemsetAsync(stats, 0, 512 * sizeof(float));
    stats_kernel<<<256, 256>>>(x);                               // kernel #1
    cvt_kernel<<<3072, 256>>>(qkv_w, proj_w, ffn_w1, ffn_w2);    // kernel #2
    bn_lif_kernel<<<PLANE / 1024, 256>>>(x, bn1_g, bn1_b, s);    // kernel #3

    cudaMemsetAsync(stats, 0, 512 * sizeof(float));              // zero for BN2 accumulation

    // kernel #4 (ncu-profiled slot): qkv GEMM with fused region means
    mma_gemm<1, 0, 0, 0, 1><<<dim3(12, 256), 256, GEMM_DSMEM>>>(s, wq, qkv_b, qkv, nullptr, nullptr, 768, 256);

    aff_topk_kernel<<<512, 64>>>();
    attn_tc_kernel<<<dim3(2, 64, 8), 128>>>(qkv, attn);

    // proj GEMM fused with residual (x2 = x + v*scale) + BN2 stats
    mma_gemm<0, 0, 1, 1, 0><<<dim3(4, 256), 256, GEMM_DSMEM>>>(attn, wp, proj_b, x2, x, scale, 256, 256);

    bn_lif_kernel<<<PLANE / 1024, 256>>>(x2, bn2_g, bn2_b, s);

    mma_gemm<1, 1, 0, 0, 0><<<dim3(16, 256), 256, GEMM_DSMEM>>>(s, w1, ffn_b1, h1, nullptr, nullptr, 1024, 256);
    // ffn2 GEMM fused with final residual (out = x2 + v*scale)
    mma_gemm<0, 0, 1, 0, 0><<<dim3(4, 256), 256, GEMM_DSMEM>>>(h1, w2, ffn_b2, out, x2, scale, 256, 1024);
}

// round 15
// speedup vs baseline: 1.0048x; 1.0009x over previous
#include <cuda_runtime.h>
#include <cuda_bf16.h>
#include <math.h>
#include <stdint.h>

typedef __nv_bfloat16 bf16;

#define T_STEPS 4
#define LTOT    4096
#define DIM     256
#define ROWS    32768
#define PLANE   2097152
#define NELEM   8388608
#define REGION  64
#define HD      32
#define TOPK    4

#define GEMM_NS 4
// A: [NS][128][20] u32, B: [NS][64][20] u32, + 2KB scratch
#define GEMM_DSMEM ((GEMM_NS * 128 * 20 + GEMM_NS * 64 * 20) * 4 + 2048)

// ---------------- scratch (device globals) ----------------
__device__ bf16  g_s[NELEM];
__device__ bf16  g_qkv[25165824];     // qkv [32768,768] bf16
__device__ bf16  g_attn[NELEM];
__device__ bf16  g_h1[33554432];      // ffn hidden [32768,1024] bf16
__device__ float g_x2[NELEM];
__device__ bf16  g_wq[196608];
__device__ bf16  g_wp[65536];
__device__ bf16  g_w1[262144];
__device__ bf16  g_w2[262144];
__device__ float g_qm[131072];
__device__ float g_km[131072];
__device__ int   g_idx[2048];
__device__ float g_stats[512];

// ---------------- asm helpers ----------------
__device__ __forceinline__ void mma16816(float* c, const unsigned* a, const unsigned* b) {
    asm volatile(
        "mma.sync.aligned.m16n8k16.row.col.f32.bf16.bf16.f32 "
        "{%0,%1,%2,%3}, {%4,%5,%6,%7}, {%8,%9}, {%0,%1,%2,%3};"
        : "+f"(c[0]), "+f"(c[1]), "+f"(c[2]), "+f"(c[3])
        : "r"(a[0]), "r"(a[1]), "r"(a[2]), "r"(a[3]), "r"(b[0]), "r"(b[1]));
}
__device__ __forceinline__ uint32_t smem_u32(const void* p) {
    uint32_t a;
    asm("{ .reg .u64 t; cvta.to.shared.u64 t, %1; cvt.u32.u64 %0, t; }" : "=r"(a) : "l"(p));
    return a;
}
__device__ __forceinline__ void cp_async16(uint32_t s, const void* g) {
    asm volatile("cp.async.cg.shared.global [%0], [%1], 16;" :: "r"(s), "l"(g));
}
__device__ __forceinline__ void cp_commit() {
    asm volatile("cp.async.commit_group;" ::: "memory");
}
template<int N>
__device__ __forceinline__ void cp_wait() {
    asm volatile("cp.async.wait_group %0;" :: "n"(N) : "memory");
}
__device__ __forceinline__ void ldsm4(unsigned& r0, unsigned& r1, unsigned& r2, unsigned& r3,
                                      uint32_t addr) {
    asm volatile("ldmatrix.sync.aligned.m8n8.x4.shared.b16 {%0,%1,%2,%3}, [%4];"
                 : "=r"(r0), "=r"(r1), "=r"(r2), "=r"(r3) : "r"(addr));
}
__device__ __forceinline__ void ldsm4t(unsigned& r0, unsigned& r1, unsigned& r2, unsigned& r3,
                                       uint32_t addr) {
    asm volatile("ldmatrix.sync.aligned.m8n8.x4.trans.shared.b16 {%0,%1,%2,%3}, [%4];"
                 : "=r"(r0), "=r"(r1), "=r"(r2), "=r"(r3) : "r"(addr));
}

// ---------------- BN1 stats (kernel #1) ----------------
__global__ void stats_kernel(const float* __restrict__ x) {
    int d = threadIdx.x;
    int r0 = blockIdx.x * 128;
    float s = 0.f, ss = 0.f;
    #pragma unroll 4
    for (int r = 0; r < 128; r++) {
        float v = x[(size_t)(r0 + r) * DIM + d];
        s += v; ss += v * v;
    }
    atomicAdd(&g_stats[d], s);
    atomicAdd(&g_stats[256 + d], ss);
}

// ---------------- weight convert (kernel #2) ----------------
__global__ void cvt_kernel(const float* __restrict__ qkv_w, const float* __restrict__ proj_w,
                           const float* __restrict__ ffn_w1, const float* __restrict__ ffn_w2) {
    int i = blockIdx.x * 256 + threadIdx.x;
    if (i < 196608) g_wq[i] = __float2bfloat16(qkv_w[i]);
    else if (i < 262144) g_wp[i - 196608] = __float2bfloat16(proj_w[i - 196608]);
    else if (i < 524288) g_w1[i - 262144] = __float2bfloat16(ffn_w1[i - 262144]);
    else g_w2[i - 524288] = __float2bfloat16(ffn_w2[i - 524288]);
}

// BN-finalize (inline) + LIF; 4 consecutive elements per thread
__global__ void bn_lif_kernel(const float* __restrict__ x,
                              const float* __restrict__ gamma, const float* __restrict__ beta,
                              bf16* __restrict__ s) {
    int i4 = blockIdx.x * blockDim.x + threadIdx.x;
    size_t i = (size_t)i4 * 4;
    int d = (int)(i & (DIM - 1));
    float sc0, sc1, sc2, sc3, sh0, sh1, sh2, sh3;
    {
        #pragma unroll
        for (int e = 0; e < 4; e++) {
            float mean = g_stats[d + e] * (1.0f / 32768.0f);
            float var  = g_stats[256 + d + e] * (1.0f / 32768.0f) - mean * mean;
            float scv = rsqrtf(var + 1e-5f) * gamma[d + e];
            float shv = beta[d + e] - mean * scv;
            if (e == 0) { sc0 = scv; sh0 = shv; }
            else if (e == 1) { sc1 = scv; sh1 = shv; }
            else if (e == 2) { sc2 = scv; sh2 = shv; }
            else { sc3 = scv; sh3 = shv; }
        }
    }
    float v0 = 0.f, v1 = 0.f, v2 = 0.f, v3 = 0.f;
    #pragma unroll
    for (int t = 0; t < T_STEPS; t++) {
        float4 xv = *(const float4*)(x + (size_t)t * PLANE + i);
        float y0 = xv.x * sc0 + sh0, y1 = xv.y * sc1 + sh1;
        float y2 = xv.z * sc2 + sh2, y3 = xv.w * sc3 + sh3;
        v0 = 0.5f * (v0 + y0); v1 = 0.5f * (v1 + y1);
        v2 = 0.5f * (v2 + y2); v3 = 0.5f * (v3 + y3);
        float s0 = (v0 >= 1.0f) ? 1.0f : 0.0f;
        float s1 = (v1 >= 1.0f) ? 1.0f : 0.0f;
        float s2 = (v2 >= 1.0f) ? 1.0f : 0.0f;
        float s3 = (v3 >= 1.0f) ? 1.0f : 0.0f;
        __nv_bfloat162 p0 = __floats2bfloat162_rn(s0, s1);
        __nv_bfloat162 p1 = __floats2bfloat162_rn(s2, s3);
        uint2 st; st.x = *(unsigned*)&p0; st.y = *(unsigned*)&p1;
        *(uint2*)(s + (size_t)t * PLANE + i) = st;
        v0 = (s0 > 0.5f) ? 0.0f : v0; v1 = (s1 > 0.5f) ? 0.0f : v1;
        v2 = (s2 > 0.5f) ? 0.0f : v2; v3 = (s3 > 0.5f) ? 0.0f : v3;
    }
}

// ---------------- 4-stage cp.async 128x64 bf16 GEMM (3 CTAs/SM target) ----------
// warps: 8 = 4(m) x 2(n); each warp 32 rows x 32 cols
template<int OUT_BF16, int GELU, int RESID, int STATS, int RSTATS>
__global__ void __launch_bounds__(256, 3)
mma_gemm(const bf16* __restrict__ A, const bf16* __restrict__ W,
         const float* __restrict__ bias, void* __restrict__ Cout,
         const float* __restrict__ resid, const float* __restrict__ scale_p,
         int N, int K) {
    extern __shared__ unsigned dynsm[];
    unsigned* Asm = dynsm;                                   // [NS][128][20]
    unsigned* Bsm = dynsm + GEMM_NS * 128 * 20;              // [NS][64][20]
    float* xsm = (float*)(dynsm + GEMM_NS * 128 * 20 + GEMM_NS * 64 * 20);  // 128 floats

    int tid = threadIdx.x;
    int warp = tid >> 5, lane = tid & 31;
    int g = lane >> 2, tig = lane & 3;
    int wm = warp >> 1, wn = warp & 1;
    int m0 = blockIdx.y * 128, n0 = blockIdx.x * 64;

    int lr = tid >> 2;            // 0..63
    int lw = (tid & 3) * 4;
    int lc = (tid & 3) * 8;

    const bf16* Ap  = A + (size_t)(m0 + lr) * K + lc;
    const bf16* Ap2 = Ap + (size_t)64 * K;
    const bf16* Wp  = W + (size_t)(n0 + lr) * K + lc;

    uint32_t sA = smem_u32(Asm), sB = smem_u32(Bsm);
    uint32_t ldoff = ((uint32_t)lr * 20 + lw) * 4;

    uint32_t aRow = ((wm * 32 + (lane & 15)) * 20 + (lane >> 4) * 4) * 4;
    uint32_t bRow = ((wn * 32 + (lane & 7) + ((lane >> 4) & 1) * 8) * 20 + ((lane >> 3) & 1) * 4) * 4;

    float acc[2][4][4];
    #pragma unroll
    for (int mi = 0; mi < 2; mi++)
        #pragma unroll
        for (int ni = 0; ni < 4; ni++)
            #pragma unroll
            for (int e = 0; e < 4; e++) acc[mi][ni][e] = 0.f;

    int n_st = K >> 5;

    #pragma unroll
    for (int st = 0; st < 3; st++) {
        size_t ko = (size_t)st << 5;
        uint32_t a0 = sA + st * 10240 + ldoff;
        uint32_t b0 = sB + st * 5120 + ldoff;
        cp_async16(a0,        Ap  + ko);
        cp_async16(a0 + 5120, Ap2 + ko);
        cp_async16(b0,        Wp  + ko);
        cp_commit();
    }

    for (int it = 0; it < n_st; it++) {
        cp_wait<2>();
        __syncthreads();
        int pre = it + 3;
        if (pre < n_st) {
            int buf = pre & 3;
            size_t ko = (size_t)pre << 5;
            uint32_t a0 = sA + buf * 10240 + ldoff;
            uint32_t b0 = sB + buf * 5120 + ldoff;
            cp_async16(a0,        Ap  + ko);
            cp_async16(a0 + 5120, Ap2 + ko);
            cp_async16(b0,        Wp  + ko);
        }
        cp_commit();

        uint32_t sAp = sA + (it & 3) * 10240;
        uint32_t sBp = sB + (it & 3) * 5120;
        #pragma unroll
        for (int ks = 0; ks < 2; ks++) {
            unsigned afr[2][4], bfr[4][2];
            #pragma unroll
            for (int mi = 0; mi < 2; mi++)
                ldsm4(afr[mi][0], afr[mi][1], afr[mi][2], afr[mi][3],
                      sAp + aRow + mi * 1280 + ks * 32);
            #pragma unroll
            for (int n2 = 0; n2 < 2; n2++)
                ldsm4(bfr[n2 * 2][0], bfr[n2 * 2][1], bfr[n2 * 2 + 1][0], bfr[n2 * 2 + 1][1],
                      sBp + bRow + n2 * 1280 + ks * 32);
            #pragma unroll
            for (int mi = 0; mi < 2; mi++)
                #pragma unroll
                for (int ni = 0; ni < 4; ni++)
                    mma16816(acc[mi][ni], afr[mi], bfr[ni]);
        }
    }

    // ---- epilogue ----
    float sc = RESID ? scale_p[0] : 0.f;
    float csum[8], csq[8];
    if (STATS || (RSTATS && n0 < 512)) {
        __syncthreads();
        if (tid < 128) xsm[tid] = 0.f;
        #pragma unroll
        for (int j = 0; j < 8; j++) { csum[j] = 0.f; csq[j] = 0.f; }
        __syncthreads();
    }

    #pragma unroll
    for (int mi = 0; mi < 2; mi++) {
        #pragma unroll
        for (int e2 = 0; e2 < 2; e2++) {
            int r = m0 + wm * 32 + mi * 16 + g + e2 * 8;
            #pragma unroll
            for (int ni = 0; ni < 4; ni++) {
                int c = n0 + wn * 32 + ni * 8 + tig * 2;
                float v0 = acc[mi][ni][e2 * 2]     + bias[c];
                float v1 = acc[mi][ni][e2 * 2 + 1] + bias[c + 1];
                if (GELU) {
                    v0 = 0.5f * v0 * (1.0f + erff(v0 * 0.70710678118654752f));
                    v1 = 0.5f * v1 * (1.0f + erff(v1 * 0.70710678118654752f));
                }
                size_t idx = (size_t)r * N + c;
                if (RESID) {
                    float2 rv = *(const float2*)(resid + idx);
                    v0 = rv.x + v0 * sc;
                    v1 = rv.y + v1 * sc;
                }
                if (STATS || RSTATS) {
                    csum[ni * 2]     += v0; csq[ni * 2]     += v0 * v0;
                    csum[ni * 2 + 1] += v1; csq[ni * 2 + 1] += v1 * v1;
                }
                if (OUT_BF16) {
                    __nv_bfloat162 pk = __floats2bfloat162_rn(v0, v1);
                    *(unsigned*)((bf16*)Cout + idx) = *(unsigned*)&pk;
                } else {
                    float2 f2; f2.x = v0; f2.y = v1;
                    *(float2*)((float*)Cout + idx) = f2;
                }
            }
        }
    }

    if (STATS) {
        // xsm[0..63] = col sums, xsm[64..127] = col sumsq
        #pragma unroll
        for (int j = 0; j < 8; j++) {
            int cl = wn * 32 + (j >> 1) * 8 + tig * 2 + (j & 1);
            atomicAdd(&xsm[cl], csum[j]);
            atomicAdd(&xsm[64 + cl], csq[j]);
        }
        __syncthreads();
        if (tid < 64) {
            atomicAdd(&g_stats[n0 + tid], xsm[tid]);
            atomicAdd(&g_stats[256 + n0 + tid], xsm[64 + tid]);
        }
    }

    if (RSTATS && n0 < 512) {
        // per-region (64-row) column sums; xsm[region*64 + col]
        #pragma unroll
        for (int j = 0; j < 8; j++) {
            csum[j] += __shfl_xor_sync(0xffffffffu, csum[j], 4);
            csum[j] += __shfl_xor_sync(0xffffffffu, csum[j], 8);
            csum[j] += __shfl_xor_sync(0xffffffffu, csum[j], 16);
        }
        int region = wm >> 1;
        if (g == 0) {
            #pragma unroll
            for (int j = 0; j < 8; j++) {
                int cl = wn * 32 + (j >> 1) * 8 + tig * 2 + (j & 1);
                atomicAdd(&xsm[region * 64 + cl], csum[j]);
            }
        }
        __syncthreads();
        if (tid < 128) {
            int rgn = tid >> 6, cl = tid & 63;
            float mv = xsm[tid] * (1.0f / 64.0f);
            int rb = (m0 >> 6) + rgn;
            int gc = n0 + cl;
            if (gc < 256) g_qm[rb * 256 + gc] = mv;
            else          g_km[rb * 256 + gc - 256] = mv;
        }
    }
}

// ---------------- affinity + top-4 routing: 64-thread blocks ----------------
__global__ void __launch_bounds__(64) aff_topk_kernel() {
    __shared__ float sq[256];
    __shared__ float aff[64];
    int blk = blockIdx.x;
    int b = blk >> 6;
    int t = threadIdx.x;

    *(float4*)&sq[t * 4] = *(const float4*)&g_qm[blk * 256 + t * 4];
    __syncthreads();

    const float* km = &g_km[((size_t)b * 64 + t) * 256];
    float s = 0.f;
    #pragma unroll 8
    for (int e = 0; e < 256; e += 4) {
        float4 kv = *(const float4*)(km + e);
        s += sq[e] * kv.x + sq[e + 1] * kv.y + sq[e + 2] * kv.z + sq[e + 3] * kv.w;
    }
    aff[t] = s;
    __syncthreads();

    if (t < 32) {
        float v0 = aff[t], v1 = aff[32 + t];
        #pragma unroll
        for (int k = 0; k < TOPK; k++) {
            float mv = (v1 > v0) ? v1 : v0;
            int   mi = (v1 > v0) ? (32 + t) : t;
            #pragma unroll
            for (int o = 16; o > 0; o >>= 1) {
                float ov = __shfl_xor_sync(0xffffffffu, mv, o);
                int   oi = __shfl_xor_sync(0xffffffffu, mi, o);
                if (ov > mv || (ov == mv && oi < mi)) { mv = ov; mi = oi; }
            }
            if (t == 0) g_idx[blk * TOPK + k] = mi;
            if (mi == t)      v0 = -INFINITY;
            if (mi == 32 + t) v1 = -INFINITY;
        }
    }
}

// ---------------- tensor-core flash attention (ldmatrix.trans V path) ----------------
#define KSTR 18
#define VSTR 20
__global__ void __launch_bounds__(128) attn_tc_kernel(const bf16* __restrict__ qkv,
                                                      bf16* __restrict__ o) {
    __shared__ unsigned sK[4][64][KSTR];
    __shared__ unsigned sV[4][64][VSTR];

    int tid = threadIdx.x;
    int w = tid >> 5, lane = tid & 31;
    int g = lane >> 2, tig = lane & 3;
    int hg = blockIdx.x, n = blockIdx.y, b = blockIdx.z;
    int h = hg * 4 + w;
    const float SCL = 0.17677669529663687f;

    unsigned (*Ks)[KSTR] = sK[w];
    unsigned (*Vs)[VSTR] = sV[w];
    uint32_t sVb = smem_u32(Vs);

    int vt = lane >> 3;
    int vrow_off = ((vt & 1) << 3) + (lane & 7);
    uint32_t vcol = ((vt >> 1) << 4);

    unsigned qf[4][2][4];
    {
        const bf16* qb = qkv + ((size_t)b * LTOT + (size_t)n * REGION) * 768 + h * HD;
        #pragma unroll
        for (int mi = 0; mi < 4; mi++)
            #pragma unroll
            for (int s = 0; s < 2; s++) {
                int d0 = s * 16 + tig * 2;
                qf[mi][s][0] = *(const unsigned*)(qb + (size_t)(mi * 16 + g) * 768 + d0);
                qf[mi][s][1] = *(const unsigned*)(qb + (size_t)(mi * 16 + g + 8) * 768 + d0);
                qf[mi][s][2] = *(const unsigned*)(qb + (size_t)(mi * 16 + g) * 768 + d0 + 8);
                qf[mi][s][3] = *(const unsigned*)(qb + (size_t)(mi * 16 + g + 8) * 768 + d0 + 8);
            }
    }

    float sO[4][4][4];
    float mrow[4][2], lrow[4][2];
    #pragma unroll
    for (int mi = 0; mi < 4; mi++) {
        #pragma unroll
        for (int nd = 0; nd < 4; nd++)
            #pragma unroll
            for (int e = 0; e < 4; e++) sO[mi][nd][e] = 0.f;
        mrow[mi][0] = -1e30f; mrow[mi][1] = -1e30f;
        lrow[mi][0] = 0.f;    lrow[mi][1] = 0.f;
    }

    for (int r = 0; r < TOPK; r++) {
        int reg = g_idx[(b * 64 + n) * TOPK + r];
        size_t kvrow = ((size_t)b * LTOT + (size_t)reg * REGION) * 768;

        #pragma unroll
        for (int rr = 0; rr < 2; rr++) {
            int key = lane * 2 + rr;
            const bf16* kb = qkv + kvrow + (size_t)key * 768 + 256 + h * HD;
            #pragma unroll
            for (int q4 = 0; q4 < 4; q4++) {
                uint4 v = *(const uint4*)(kb + q4 * 8);
                Ks[key][q4 * 4 + 0] = v.x; Ks[key][q4 * 4 + 1] = v.y;
                Ks[key][q4 * 4 + 2] = v.z; Ks[key][q4 * 4 + 3] = v.w;
            }
        }
        #pragma unroll
        for (int kk = 0; kk < 2; kk++) {
            int key = kk * 32 + lane;
            const bf16* vb = qkv + kvrow + (size_t)key * 768 + 512 + h * HD;
            #pragma unroll
            for (int q4 = 0; q4 < 4; q4++) {
                uint4 v = *(const uint4*)(vb + q4 * 8);
                *(uint4*)&Vs[key][q4 * 4] = v;
            }
        }
        __syncwarp();

        #pragma unroll
        for (int sc = 0; sc < 2; sc++) {
            float sS[4][4][4];
            #pragma unroll
            for (int mi = 0; mi < 4; mi++)
                #pragma unroll
                for (int nj = 0; nj < 4; nj++)
                    #pragma unroll
                    for (int e = 0; e < 4; e++) sS[mi][nj][e] = 0.f;

            #pragma unroll
            for (int s = 0; s < 2; s++) {
                unsigned bfr[4][2];
                #pragma unroll
                for (int nj = 0; nj < 4; nj++) {
                    int kr = sc * 32 + nj * 8 + g;
                    bfr[nj][0] = Ks[kr][s * 8 + tig];
                    bfr[nj][1] = Ks[kr][s * 8 + tig + 4];
                }
                #pragma unroll
                for (int mi = 0; mi < 4; mi++)
                    #pragma unroll
                    for (int nj = 0; nj < 4; nj++)
                        mma16816(sS[mi][nj], qf[mi][s], bfr[nj]);
            }

            #pragma unroll
            for (int mi = 0; mi < 4; mi++) {
                #pragma unroll
                for (int hf = 0; hf < 2; hf++) {
                    float mx = -1e30f;
                    #pragma unroll
                    for (int nj = 0; nj < 4; nj++) {
                        float v0 = sS[mi][nj][hf * 2] * SCL;
                        float v1 = sS[mi][nj][hf * 2 + 1] * SCL;
                        sS[mi][nj][hf * 2] = v0; sS[mi][nj][hf * 2 + 1] = v1;
                        mx = fmaxf(mx, fmaxf(v0, v1));
                    }
                    mx = fmaxf(mx, __shfl_xor_sync(0xffffffffu, mx, 1));
                    mx = fmaxf(mx, __shfl_xor_sync(0xffffffffu, mx, 2));
                    float mnew = fmaxf(mrow[mi][hf], mx);
                    float alpha = __expf(mrow[mi][hf] - mnew);
                    mrow[mi][hf] = mnew;
                    float lsum = 0.f;
                    #pragma unroll
                    for (int nj = 0; nj < 4; nj++) {
                        float p0 = __expf(sS[mi][nj][hf * 2] - mnew);
                        float p1 = __expf(sS[mi][nj][hf * 2 + 1] - mnew);
                        sS[mi][nj][hf * 2] = p0; sS[mi][nj][hf * 2 + 1] = p1;
                        lsum += p0 + p1;
                    }
                    lsum += __shfl_xor_sync(0xffffffffu, lsum, 1);
                    lsum += __shfl_xor_sync(0xffffffffu, lsum, 2);
                    lrow[mi][hf] = lrow[mi][hf] * alpha + lsum;
                    #pragma unroll
                    for (int nd = 0; nd < 4; nd++) {
                        sO[mi][nd][hf * 2]     *= alpha;
                        sO[mi][nd][hf * 2 + 1] *= alpha;
                    }
                }
            }

            #pragma unroll
            for (int s = 0; s < 2; s++) {
                unsigned bfr[4][2];
                int k0 = sc * 32 + s * 16;
                uint32_t rowaddr = sVb + (uint32_t)(k0 + vrow_off) * (VSTR * 4);
                ldsm4t(bfr[0][0], bfr[0][1], bfr[1][0], bfr[1][1], rowaddr + vcol);
                ldsm4t(bfr[2][0], bfr[2][1], bfr[3][0], bfr[3][1], rowaddr + vcol + 32);
                #pragma unroll
                for (int mi = 0; mi < 4; mi++) {
                    unsigned af[4];
                    __nv_bfloat162 t0 = __floats2bfloat162_rn(sS[mi][2 * s][0], sS[mi][2 * s][1]);
                    __nv_bfloat162 t1 = __floats2bfloat162_rn(sS[mi][2 * s][2], sS[mi][2 * s][3]);
                    __nv_bfloat162 t2 = __floats2bfloat162_rn(sS[mi][2 * s + 1][0], sS[mi][2 * s + 1][1]);
                    __nv_bfloat162 t3 = __floats2bfloat162_rn(sS[mi][2 * s + 1][2], sS[mi][2 * s + 1][3]);
                    af[0] = *(unsigned*)&t0; af[1] = *(unsigned*)&t1;
                    af[2] = *(unsigned*)&t2; af[3] = *(unsigned*)&t3;
                    #pragma unroll
                    for (int nd = 0; nd < 4; nd++)
                        mma16816(sO[mi][nd], af, bfr[nd]);
                }
            }
        }
        __syncwarp();
    }

    #pragma unroll
    for (int mi = 0; mi < 4; mi++) {
        float inv0 = 1.0f / lrow[mi][0];
        float inv1 = 1.0f / lrow[mi][1];
        #pragma unroll
        for (int hf = 0; hf < 2; hf++) {
            float inv = hf ? inv1 : inv0;
            size_t row = (size_t)b * LTOT + (size_t)n * REGION + mi * 16 + g + hf * 8;
            #pragma unroll
            for (int nd = 0; nd < 4; nd++) {
                float v0 = sO[mi][nd][hf * 2] * inv;
                float v1 = sO[mi][nd][hf * 2 + 1] * inv;
                __nv_bfloat162 p = __floats2bfloat162_rn(v0, v1);
                *(unsigned*)(o + row * DIM + h * HD + nd * 8 + tig * 2) = *(unsigned*)&p;
            }
        }
    }
}

// ---------------- host launcher ----------------
extern "C" void kernel_launch(void* const* d_in, const int* in_sizes, int n_in,
                              void* d_out, int out_size) {
    const float* x      = (const float*)d_in[0];
    const float* bn1_g  = (const float*)d_in[1];
    const float* bn1_b  = (const float*)d_in[2];
    const float* bn2_g  = (const float*)d_in[3];
    const float* bn2_b  = (const float*)d_in[4];
    const float* qkv_w  = (const float*)d_in[5];
    const float* qkv_b  = (const float*)d_in[6];
    const float* proj_w = (const float*)d_in[7];
    const float* proj_b = (const float*)d_in[8];
    const float* ffn_w1 = (const float*)d_in[9];
    const float* ffn_b1 = (const float*)d_in[10];
    const float* ffn_w2 = (const float*)d_in[11];
    const float* ffn_b2 = (const float*)d_in[12];
    const float* scale  = (const float*)d_in[13];
    float* out = (float*)d_out;

    cudaFuncSetAttribute(mma_gemm<1, 0, 0, 0, 1>, cudaFuncAttributeMaxDynamicSharedMemorySize, GEMM_DSMEM);
    cudaFuncSetAttribute(mma_gemm<0, 0, 1, 1, 0>, cudaFuncAttributeMaxDynamicSharedMemorySize, GEMM_DSMEM);
    cudaFuncSetAttribute(mma_gemm<1, 1, 0, 0, 0>, cudaFuncAttributeMaxDynamicSharedMemorySize, GEMM_DSMEM);
    cudaFuncSetAttribute(mma_gemm<0, 0, 1, 0, 0>, cudaFuncAttributeMaxDynamicSharedMemorySize, GEMM_DSMEM);

    bf16*  s    = nullptr; cudaGetSymbolAddress((void**)&s,    g_s);
    bf16*  qkv  = nullptr; cudaGetSymbolAddress((void**)&qkv,  g_qkv);
    bf16*  attn = nullptr; cudaGetSymbolAddress((void**)&attn, g_attn);
    bf16*  h1   = nullptr; cudaGetSymbolAddress((void**)&h1,   g_h1);
    float* x2   = nullptr; cudaGetSymbolAddress((void**)&x2,   g_x2);
    bf16*  wq   = nullptr; cudaGetSymbolAddress((void**)&wq,   g_wq);
    bf16*  wp   = nullptr; cudaGetSymbolAddress((void**)&wp,   g_wp);
    bf16*  w1   = nullptr; cudaGetSymbolAddress((void**)&w1,   g_w1);
    bf16*  w2   = nullptr; cudaGetSymbolAddress((void**)&w2,   g_w2);
    float* stats = nullptr; cudaGetSymbolAddress((void**)&stats, g_stats);

    // ---- attention branch ----
    cudaMemsetAsync(stats, 0, 512 * sizeof(float));
    stats_kernel<<<256, 256>>>(x);                               // kernel #1
    cvt_kernel<<<3072, 256>>>(qkv_w, proj_w, ffn_w1, ffn_w2);    // kernel #2
    bn_lif_kernel<<<PLANE / 1024, 256>>>(x, bn1_g, bn1_b, s);    // kernel #3

    cudaMemsetAsync(stats, 0, 512 * sizeof(float));              // zero for BN2 accumulation

    // kernel #4 (ncu-profiled slot): qkv GEMM with fused region means
    mma_gemm<1, 0, 0, 0, 1><<<dim3(12, 256), 256, GEMM_DSMEM>>>(s, wq, qkv_b, qkv, nullptr, nullptr, 768, 256);

    aff_topk_kernel<<<512, 64>>>();
    attn_tc_kernel<<<dim3(2, 64, 8), 128>>>(qkv, attn);

    // proj GEMM fused with residual (x2 = x + v*scale) + BN2 stats
    mma_gemm<0, 0, 1, 1, 0><<<dim3(4, 256), 256, GEMM_DSMEM>>>(attn, wp, proj_b, x2, x, scale, 256, 256);

    bn_lif_kernel<<<PLANE / 1024, 256>>>(x2, bn2_g, bn2_b, s);

    mma_gemm<1, 1, 0, 0, 0><<<dim3(16, 256), 256, GEMM_DSMEM>>>(s, w1, ffn_b1, h1, nullptr, nullptr, 1024, 256);
    // ffn2 GEMM fused with final residual (out = x2 + v*scale)
    mma_gemm<0, 0, 1, 0, 0><<<dim3(4, 256), 256, GEMM_DSMEM>>>(h1, w2, ffn_b2, out, x2, scale, 256, 1024);
}